// round 10
// baseline (speedup 1.0000x reference)
#include <cuda_runtime.h>

// Problem constants (fixed by the reference):
//   x: [B, 96, 128, 128] fp32, depthwise 3x3, stride 1, pad 1
#define C_DIM 96
#define HW 128
#define PLANE (HW * HW)          // 16384
#define CR 24                    // C_DIM / 4
#define WDYN_PER_B (C_DIM * 9)   // 864
#define BN_EPS 1e-5f
#define MAX_B 64
#define CHUNK_B 8                // samples per L2-resident chunk (8*6.3MB = 50MB)

// Scratch (allocation-free rule: __device__ globals)
__device__ float g_pooled[MAX_B * C_DIM];
__device__ float g_wdyn[MAX_B * WDYN_PER_B];

// ---------------------------------------------------------------------------
// Kernel 1: global average pool over each (b,c) plane. (80.9% DRAM measured)
// Launched per chunk: grid = nb*C_DIM planes, pointers pre-offset.
// ---------------------------------------------------------------------------
__global__ __launch_bounds__(256) void pool_kernel(const float* __restrict__ x,
                                                   float* __restrict__ pooled) {
    const int plane = blockIdx.x;
    const float4* xp = reinterpret_cast<const float4*>(x + (size_t)plane * PLANE);
    float s = 0.f;
#pragma unroll 4
    for (int i = threadIdx.x; i < PLANE / 4; i += 256) {
        float4 v = xp[i];
        s += (v.x + v.y) + (v.z + v.w);
    }
#pragma unroll
    for (int o = 16; o > 0; o >>= 1) s += __shfl_xor_sync(0xffffffffu, s, o);

    __shared__ float ws[8];
    if ((threadIdx.x & 31) == 0) ws[threadIdx.x >> 5] = s;
    __syncthreads();
    if (threadIdx.x < 8) {
        float t = ws[threadIdx.x];
#pragma unroll
        for (int o = 4; o > 0; o >>= 1) t += __shfl_xor_sync(0xffu, t, o);
        if (threadIdx.x == 0) pooled[plane] = t * (1.f / (float)PLANE);
    }
}

// ---------------------------------------------------------------------------
// Kernel 2: dynamic weight generation. One block per batch sample. (tiny)
// ---------------------------------------------------------------------------
__global__ __launch_bounds__(256) void weight_kernel(
    const float* __restrict__ pooled,
    const float* __restrict__ w1,      // [CR, C_DIM]
    const float* __restrict__ gamma,
    const float* __restrict__ beta,
    const float* __restrict__ rmean,
    const float* __restrict__ rvar,
    const float* __restrict__ w2,      // [WDYN_PER_B, CR]
    const float* __restrict__ b2,
    float* __restrict__ wdyn) {
    const int b = blockIdx.x;
    __shared__ float p[C_DIM];
    __shared__ float h1[CR];
    const int tid = threadIdx.x;

    if (tid < C_DIM) p[tid] = pooled[b * C_DIM + tid];
    __syncthreads();

    if (tid < CR) {
        float s = 0.f;
        const float* wr = w1 + tid * C_DIM;
#pragma unroll 8
        for (int c = 0; c < C_DIM; c++) s += p[c] * wr[c];
        s = (s - rmean[tid]) * rsqrtf(rvar[tid] + BN_EPS) * gamma[tid] + beta[tid];
        h1[tid] = 1.f / (1.f + __expf(-s));
    }
    __syncthreads();

    for (int o = tid; o < WDYN_PER_B; o += 256) {
        float s = b2[o];
        const float* wr = w2 + o * CR;
#pragma unroll
        for (int j = 0; j < CR; j++) s += h1[j] * wr[j];
        wdyn[b * WDYN_PER_B + o] = s;
    }
}

// ---------------------------------------------------------------------------
// Kernel 3: per-sample depthwise 3x3 conv — cp.async double-buffered pipeline.
// One block per plane; 4 tiles of 32 rows, 2 smem buffers. Chunked launch:
// reads hit L2 (pool just streamed them). __stcs keeps write footprint light.
// ---------------------------------------------------------------------------
#define ROWS 32
#define TROWS (ROWS + 2)   // 34
#define TW 132             // 128 data cols + pad (row stride 528B, 16B-aligned)

__device__ __forceinline__ void cp16(float* dst, const float* src) {
    unsigned d = (unsigned)__cvta_generic_to_shared(dst);
    asm volatile("cp.async.cg.shared.global [%0], [%1], 16;" :: "r"(d), "l"(src) : "memory");
}
#define CP_COMMIT() asm volatile("cp.async.commit_group;" ::: "memory")
#define CP_WAIT(n)  asm volatile("cp.async.wait_group %0;" :: "n"(n) : "memory")

__global__ __launch_bounds__(256) void dwconv_kernel(
    const float* __restrict__ x,
    const float* __restrict__ wdyn,
    const float* __restrict__ bias,
    float* __restrict__ out) {
    const int plane = blockIdx.x;          // (b within chunk)*C + c
    const int ch = plane % C_DIM;
    const int tid = threadIdx.y * 32 + threadIdx.x;
    const int lane = threadIdx.x;

    __shared__ float tile[2][TROWS][TW];

    const float* xp = x + (size_t)plane * PLANE;
    float* op = out + (size_t)plane * PLANE;

    auto fill = [&](int buf, int row0) {
#pragma unroll
        for (int k = 0; k < 4; k++) {
            const int i = tid + k * 256;          // 0..1023
            const int r = i >> 5, cq = i & 31;
            const int gr = row0 - 1 + r;
            float* dst = &tile[buf][r][cq * 4];
            if ((unsigned)gr < (unsigned)HW)
                cp16(dst, xp + gr * HW + cq * 4);
            else
                *reinterpret_cast<float4*>(dst) = make_float4(0.f, 0.f, 0.f, 0.f);
        }
        if (tid < TROWS * 32 - 1024) {            // rows 32,33
            const int i = tid + 1024;
            const int r = i >> 5, cq = i & 31;
            const int gr = row0 - 1 + r;
            float* dst = &tile[buf][r][cq * 4];
            if ((unsigned)gr < (unsigned)HW)
                cp16(dst, xp + gr * HW + cq * 4);
            else
                *reinterpret_cast<float4*>(dst) = make_float4(0.f, 0.f, 0.f, 0.f);
        }
    };

    fill(0, 0);
    CP_COMMIT();

    float w[9];
    const float* wp = wdyn + (size_t)plane * 9;
#pragma unroll
    for (int i = 0; i < 9; i++) w[i] = __ldg(wp + i);
    const float bv = __ldg(bias + ch);

    fill(1, ROWS);
    CP_COMMIT();

    const int cx = threadIdx.x * 4;

    auto compute = [&](int buf, int row0) {
#pragma unroll
        for (int j = 0; j < 4; j++) {
            const int rt = threadIdx.y * 4 + j;
            float a0 = bv, a1 = bv, a2 = bv, a3 = bv;
#pragma unroll
            for (int dy = 0; dy < 3; dy++) {
                const float4 v = *reinterpret_cast<const float4*>(&tile[buf][rt + dy][cx]);
                float vl = __shfl_up_sync(0xffffffffu, v.w, 1);
                float vr = __shfl_down_sync(0xffffffffu, v.x, 1);
                if (lane == 0)  vl = 0.f;
                if (lane == 31) vr = 0.f;
                const float w0 = w[dy * 3 + 0], w1_ = w[dy * 3 + 1], w2_ = w[dy * 3 + 2];
                a0 += vl  * w0 + v.x * w1_ + v.y * w2_;
                a1 += v.x * w0 + v.y * w1_ + v.z * w2_;
                a2 += v.y * w0 + v.z * w1_ + v.w * w2_;
                a3 += v.z * w0 + v.w * w1_ + vr  * w2_;
            }
            float4 o; o.x = a0; o.y = a1; o.z = a2; o.w = a3;
            __stcs(reinterpret_cast<float4*>(op + (row0 + rt) * HW + cx), o);
        }
    };

    CP_WAIT(1); __syncthreads();
    compute(0, 0);
    __syncthreads();
    fill(0, 2 * ROWS); CP_COMMIT();

    CP_WAIT(1); __syncthreads();
    compute(1, ROWS);
    __syncthreads();
    fill(1, 3 * ROWS); CP_COMMIT();

    CP_WAIT(1); __syncthreads();
    compute(0, 2 * ROWS);
    __syncthreads();

    CP_WAIT(0); __syncthreads();
    compute(1, 3 * ROWS);
}

// ---------------------------------------------------------------------------
// Launch: chunk samples so the conv pass re-reads L2-resident data.
// ---------------------------------------------------------------------------
extern "C" void kernel_launch(void* const* d_in, const int* in_sizes, int n_in,
                              void* d_out, int out_size) {
    const float* x     = (const float*)d_in[0];
    const float* w1    = (const float*)d_in[1];
    const float* gamma = (const float*)d_in[2];
    const float* beta  = (const float*)d_in[3];
    const float* rmean = (const float*)d_in[4];
    const float* rvar  = (const float*)d_in[5];
    const float* w2    = (const float*)d_in[6];
    const float* b2    = (const float*)d_in[7];
    const float* bias  = (const float*)d_in[8];
    float* out = (float*)d_out;

    const int B = in_sizes[0] / (C_DIM * PLANE);

    float* pooled;
    float* wdyn;
    cudaGetSymbolAddress((void**)&pooled, g_pooled);
    cudaGetSymbolAddress((void**)&wdyn, g_wdyn);

    dim3 cblock(32, 8);
    for (int b0 = 0; b0 < B; b0 += CHUNK_B) {
        const int nb = (B - b0 < CHUNK_B) ? (B - b0) : CHUNK_B;
        const size_t xoff = (size_t)b0 * C_DIM * PLANE;
        pool_kernel<<<nb * C_DIM, 256>>>(x + xoff, pooled + b0 * C_DIM);
        weight_kernel<<<nb, 256>>>(pooled + b0 * C_DIM, w1, gamma, beta, rmean,
                                   rvar, w2, b2, wdyn + (size_t)b0 * WDYN_PER_B);
        dwconv_kernel<<<nb * C_DIM, cblock>>>(x + xoff,
                                              wdyn + (size_t)b0 * WDYN_PER_B,
                                              bias, out + xoff);
    }
}

// round 11
// speedup vs baseline: 1.3912x; 1.3912x over previous
#include <cuda_runtime.h>

// Problem constants (fixed by the reference):
//   x: [B, 96, 128, 128] fp32, depthwise 3x3, stride 1, pad 1
#define C_DIM 96
#define HW 128
#define PLANE (HW * HW)          // 16384
#define CR 24                    // C_DIM / 4
#define WDYN_PER_B (C_DIM * 9)   // 864
#define BN_EPS 1e-5f
#define MAX_B 64

// Scratch (allocation-free rule: __device__ globals)
__device__ float g_pooled[MAX_B * C_DIM];
__device__ float g_wdyn[MAX_B * WDYN_PER_B];

// ---------------------------------------------------------------------------
// Kernel 1: global average pool over each (b,c) plane. (80.9% DRAM — keep,
// full-size grid only: chunked 768-block grids measured at 57% DRAM.)
// ---------------------------------------------------------------------------
__global__ __launch_bounds__(256) void pool_kernel(const float* __restrict__ x,
                                                   float* __restrict__ pooled) {
    const int plane = blockIdx.x;
    const float4* xp = reinterpret_cast<const float4*>(x + (size_t)plane * PLANE);
    float s = 0.f;
#pragma unroll 4
    for (int i = threadIdx.x; i < PLANE / 4; i += 256) {
        float4 v = xp[i];
        s += (v.x + v.y) + (v.z + v.w);
    }
#pragma unroll
    for (int o = 16; o > 0; o >>= 1) s += __shfl_xor_sync(0xffffffffu, s, o);

    __shared__ float ws[8];
    if ((threadIdx.x & 31) == 0) ws[threadIdx.x >> 5] = s;
    __syncthreads();
    if (threadIdx.x < 8) {
        float t = ws[threadIdx.x];
#pragma unroll
        for (int o = 4; o > 0; o >>= 1) t += __shfl_xor_sync(0xffu, t, o);
        if (threadIdx.x == 0) pooled[plane] = t * (1.f / (float)PLANE);
    }
}

// ---------------------------------------------------------------------------
// Kernel 2: dynamic weight generation. One block per batch sample. (tiny)
// ---------------------------------------------------------------------------
__global__ __launch_bounds__(256) void weight_kernel(
    const float* __restrict__ pooled,
    const float* __restrict__ w1,      // [CR, C_DIM]
    const float* __restrict__ gamma,
    const float* __restrict__ beta,
    const float* __restrict__ rmean,
    const float* __restrict__ rvar,
    const float* __restrict__ w2,      // [WDYN_PER_B, CR]
    const float* __restrict__ b2,
    float* __restrict__ wdyn) {
    const int b = blockIdx.x;
    __shared__ float p[C_DIM];
    __shared__ float h1[CR];
    const int tid = threadIdx.x;

    if (tid < C_DIM) p[tid] = pooled[b * C_DIM + tid];
    __syncthreads();

    if (tid < CR) {
        float s = 0.f;
        const float* wr = w1 + tid * C_DIM;
#pragma unroll 8
        for (int c = 0; c < C_DIM; c++) s += p[c] * wr[c];
        s = (s - rmean[tid]) * rsqrtf(rvar[tid] + BN_EPS) * gamma[tid] + beta[tid];
        h1[tid] = 1.f / (1.f + __expf(-s));
    }
    __syncthreads();

    for (int o = tid; o < WDYN_PER_B; o += 256) {
        float s = b2[o];
        const float* wr = w2 + o * CR;
#pragma unroll
        for (int j = 0; j < CR; j++) s += h1[j] * wr[j];
        wdyn[b * WDYN_PER_B + o] = s;
    }
}

// ---------------------------------------------------------------------------
// Kernel 3: per-sample depthwise 3x3 conv — cp.async TRIPLE-buffered pipeline.
// One block per plane; 8 tiles of 16 rows, 3 smem buffers (2 tiles in flight).
// smem 3*18*132*4 = 28.5KB -> 8 CTAs/SM = 64 warps (full warp cap), vs 48
// for the 32-row double buffer. Column halos (zero pad) via 2 shfls per row.
// ---------------------------------------------------------------------------
#define ROWS 16
#define TROWS (ROWS + 2)   // 18
#define TW 132             // 128 data cols + pad (row stride 528B, 16B-aligned)
#define NTILES (HW / ROWS) // 8

__device__ __forceinline__ void cp16(float* dst, const float* src) {
    unsigned d = (unsigned)__cvta_generic_to_shared(dst);
    asm volatile("cp.async.cg.shared.global [%0], [%1], 16;" :: "r"(d), "l"(src) : "memory");
}
#define CP_COMMIT() asm volatile("cp.async.commit_group;" ::: "memory")
#define CP_WAIT1()  asm volatile("cp.async.wait_group 1;" ::: "memory")
#define CP_WAIT0()  asm volatile("cp.async.wait_group 0;" ::: "memory")

__global__ __launch_bounds__(256) void dwconv_kernel(
    const float* __restrict__ x,
    const float* __restrict__ wdyn,
    const float* __restrict__ bias,
    float* __restrict__ out) {
    const int plane = blockIdx.x;          // b*C + c
    const int ch = plane % C_DIM;
    const int tid = threadIdx.y * 32 + threadIdx.x;
    const int lane = threadIdx.x;

    __shared__ float tile[3][TROWS][TW];

    const float* xp = x + (size_t)plane * PLANE;
    float* op = out + (size_t)plane * PLANE;

    // tile row r (0..17) of the tile starting at output row row0 = x row row0-1+r
    auto fill = [&](int buf, int row0) {
#pragma unroll
        for (int k = 0; k < 2; k++) {
            const int i = tid + k * 256;          // 0..511
            const int r = i >> 5, cq = i & 31;
            const int gr = row0 - 1 + r;
            float* dst = &tile[buf][r][cq * 4];
            if ((unsigned)gr < (unsigned)HW)
                cp16(dst, xp + gr * HW + cq * 4);
            else
                *reinterpret_cast<float4*>(dst) = make_float4(0.f, 0.f, 0.f, 0.f);
        }
        if (tid < TROWS * 32 - 512) {             // rows 16,17 (64 float4s)
            const int i = tid + 512;
            const int r = i >> 5, cq = i & 31;
            const int gr = row0 - 1 + r;
            float* dst = &tile[buf][r][cq * 4];
            if ((unsigned)gr < (unsigned)HW)
                cp16(dst, xp + gr * HW + cq * 4);
            else
                *reinterpret_cast<float4*>(dst) = make_float4(0.f, 0.f, 0.f, 0.f);
        }
    };

    // prologue: 2 tiles in flight before first compute
    fill(0, 0);
    CP_COMMIT();

    // per-channel dynamic 3x3 weights (broadcast; hides under cp.asyncs)
    float w[9];
    const float* wp = wdyn + (size_t)plane * 9;
#pragma unroll
    for (int i = 0; i < 9; i++) w[i] = __ldg(wp + i);
    const float bv = __ldg(bias + ch);

    fill(1, ROWS);
    CP_COMMIT();

    const int cx = threadIdx.x * 4;

    auto compute = [&](int buf, int row0) {
#pragma unroll
        for (int j = 0; j < 2; j++) {
            const int rt = threadIdx.y * 2 + j;   // output row within tile
            float a0 = bv, a1 = bv, a2 = bv, a3 = bv;
#pragma unroll
            for (int dy = 0; dy < 3; dy++) {
                const float4 v = *reinterpret_cast<const float4*>(&tile[buf][rt + dy][cx]);
                float vl = __shfl_up_sync(0xffffffffu, v.w, 1);
                float vr = __shfl_down_sync(0xffffffffu, v.x, 1);
                if (lane == 0)  vl = 0.f;   // x col -1 (zero pad)
                if (lane == 31) vr = 0.f;   // x col 128 (zero pad)
                const float w0 = w[dy * 3 + 0], w1_ = w[dy * 3 + 1], w2_ = w[dy * 3 + 2];
                a0 += vl  * w0 + v.x * w1_ + v.y * w2_;
                a1 += v.x * w0 + v.y * w1_ + v.z * w2_;
                a2 += v.y * w0 + v.z * w1_ + v.w * w2_;
                a3 += v.z * w0 + v.w * w1_ + vr  * w2_;
            }
            float4 o; o.x = a0; o.y = a1; o.z = a2; o.w = a3;
            __stcs(reinterpret_cast<float4*>(op + (row0 + rt) * HW + cx), o);
        }
    };

    int buf = 0;
#pragma unroll
    for (int t = 0; t < NTILES; t++) {
        if (t < NTILES - 1) { CP_WAIT1(); } else { CP_WAIT0(); }
        __syncthreads();
        compute(buf, t * ROWS);
        __syncthreads();
        if (t + 2 < NTILES) {
            const int nb = (buf + 2) % 3;
            fill(nb, (t + 2) * ROWS);
            CP_COMMIT();
        }
        buf = (buf + 1) % 3;
    }
}

// ---------------------------------------------------------------------------
// Launch (non-chunked — full-size grids; chunking measured as a regression)
// ---------------------------------------------------------------------------
extern "C" void kernel_launch(void* const* d_in, const int* in_sizes, int n_in,
                              void* d_out, int out_size) {
    const float* x     = (const float*)d_in[0];
    const float* w1    = (const float*)d_in[1];
    const float* gamma = (const float*)d_in[2];
    const float* beta  = (const float*)d_in[3];
    const float* rmean = (const float*)d_in[4];
    const float* rvar  = (const float*)d_in[5];
    const float* w2    = (const float*)d_in[6];
    const float* b2    = (const float*)d_in[7];
    const float* bias  = (const float*)d_in[8];
    float* out = (float*)d_out;

    const int B = in_sizes[0] / (C_DIM * PLANE);
    const int planes = B * C_DIM;

    float* pooled;
    float* wdyn;
    cudaGetSymbolAddress((void**)&pooled, g_pooled);
    cudaGetSymbolAddress((void**)&wdyn, g_wdyn);

    pool_kernel<<<planes, 256>>>(x, pooled);
    weight_kernel<<<B, 256>>>(pooled, w1, gamma, beta, rmean, rvar, w2, b2, wdyn);
    dim3 block(32, 8);
    dwconv_kernel<<<planes, block>>>(x, wdyn, bias, out);
}

// round 13
// speedup vs baseline: 1.4520x; 1.0438x over previous
#include <cuda_runtime.h>

// Problem constants (fixed by the reference):
//   x: [B, 96, 128, 128] fp32, depthwise 3x3, stride 1, pad 1
#define C_DIM 96
#define HW 128
#define PLANE (HW * HW)          // 16384
#define CR 24                    // C_DIM / 4
#define WDYN_PER_B (C_DIM * 9)   // 864
#define BN_EPS 1e-5f
#define MAX_B 64

// Scratch (allocation-free rule: __device__ globals)
__device__ float g_pooled[MAX_B * C_DIM];
__device__ float g_wdyn[MAX_B * WDYN_PER_B];
__device__ int   g_cnt[MAX_B];          // per-sample completion counters

// ---------------------------------------------------------------------------
// Kernel 1: global average pool over each (b,c) plane, with fused dynamic-
// weight tail: the block that completes its sample last (atomic counter hits
// C_DIM) computes that sample's 864 conv weights in-block. Removes the
// separate weight kernel and its serialization bubble.
// ---------------------------------------------------------------------------
__global__ __launch_bounds__(256) void pool_kernel(
    const float* __restrict__ x,
    const float* __restrict__ w1,      // [CR, C_DIM]
    const float* __restrict__ gamma,
    const float* __restrict__ beta,
    const float* __restrict__ rmean,
    const float* __restrict__ rvar,
    const float* __restrict__ w2,      // [WDYN_PER_B, CR]
    const float* __restrict__ b2,
    float* __restrict__ pooled,
    float* __restrict__ wdyn,
    int* __restrict__ cnt) {
    const int plane = blockIdx.x;
    const int b = plane / C_DIM;
    const int tid = threadIdx.x;

    const float4* xp = reinterpret_cast<const float4*>(x + (size_t)plane * PLANE);
    float s = 0.f;
#pragma unroll 4
    for (int i = tid; i < PLANE / 4; i += 256) {
        float4 v = xp[i];
        s += (v.x + v.y) + (v.z + v.w);
    }
#pragma unroll
    for (int o = 16; o > 0; o >>= 1) s += __shfl_xor_sync(0xffffffffu, s, o);

    __shared__ float ws[8];
    __shared__ int last;
    if ((tid & 31) == 0) ws[tid >> 5] = s;
    __syncthreads();
    if (tid < 8) {
        float t = ws[tid];
#pragma unroll
        for (int o = 4; o > 0; o >>= 1) t += __shfl_xor_sync(0xffu, t, o);
        if (tid == 0) {
            pooled[plane] = t * (1.f / (float)PLANE);
            __threadfence();                       // publish before counting
            const int old = atomicAdd(&cnt[b], 1);
            last = (old == C_DIM - 1) ? 1 : 0;
        }
    }
    __syncthreads();
    if (!last) return;

    // ---- this block is the last finisher for sample b: compute weights ----
    __shared__ float p[C_DIM];
    __shared__ float h1[CR];
    if (tid < C_DIM) p[tid] = __ldcg(&pooled[b * C_DIM + tid]);  // bypass L1
    __syncthreads();
    if (tid < CR) {
        float t = 0.f;
        const float* wr = w1 + tid * C_DIM;
#pragma unroll 8
        for (int c = 0; c < C_DIM; c++) t += p[c] * wr[c];
        t = (t - rmean[tid]) * rsqrtf(rvar[tid] + BN_EPS) * gamma[tid] + beta[tid];
        h1[tid] = 1.f / (1.f + __expf(-t));
    }
    __syncthreads();
    for (int o = tid; o < WDYN_PER_B; o += 256) {
        float t = b2[o];
        const float* wr = w2 + o * CR;
#pragma unroll
        for (int j = 0; j < CR; j++) t += h1[j] * wr[j];
        wdyn[b * WDYN_PER_B + o] = t;
    }
}

// ---------------------------------------------------------------------------
// Kernel 2: per-sample depthwise 3x3 conv — cp.async triple-buffered pipeline.
// Planes processed in REVERSE order: the tail of x (last-read by pool) is
// still L2-resident at conv start, so a large slice of conv reads hit L2.
// __stcs output stores are evict-first, preserving x residency.
// ---------------------------------------------------------------------------
#define ROWS 16
#define TROWS (ROWS + 2)   // 18
#define TW 132             // 128 data cols + pad (row stride 528B, 16B-aligned)
#define NTILES (HW / ROWS) // 8

__device__ __forceinline__ void cp16(float* dst, const float* src) {
    unsigned d = (unsigned)__cvta_generic_to_shared(dst);
    asm volatile("cp.async.cg.shared.global [%0], [%1], 16;" :: "r"(d), "l"(src) : "memory");
}
#define CP_COMMIT() asm volatile("cp.async.commit_group;" ::: "memory")
#define CP_WAIT1()  asm volatile("cp.async.wait_group 1;" ::: "memory")
#define CP_WAIT0()  asm volatile("cp.async.wait_group 0;" ::: "memory")

__global__ __launch_bounds__(256) void dwconv_kernel(
    const float* __restrict__ x,
    const float* __restrict__ wdyn,
    const float* __restrict__ bias,
    float* __restrict__ out) {
    const int plane = gridDim.x - 1 - blockIdx.x;   // REVERSE order for L2 reuse
    const int ch = plane % C_DIM;
    const int tid = threadIdx.y * 32 + threadIdx.x;
    const int lane = threadIdx.x;

    __shared__ float tile[3][TROWS][TW];

    const float* xp = x + (size_t)plane * PLANE;
    float* op = out + (size_t)plane * PLANE;

    auto fill = [&](int buf, int row0) {
#pragma unroll
        for (int k = 0; k < 2; k++) {
            const int i = tid + k * 256;          // 0..511
            const int r = i >> 5, cq = i & 31;
            const int gr = row0 - 1 + r;
            float* dst = &tile[buf][r][cq * 4];
            if ((unsigned)gr < (unsigned)HW)
                cp16(dst, xp + gr * HW + cq * 4);
            else
                *reinterpret_cast<float4*>(dst) = make_float4(0.f, 0.f, 0.f, 0.f);
        }
        if (tid < TROWS * 32 - 512) {             // rows 16,17
            const int i = tid + 512;
            const int r = i >> 5, cq = i & 31;
            const int gr = row0 - 1 + r;
            float* dst = &tile[buf][r][cq * 4];
            if ((unsigned)gr < (unsigned)HW)
                cp16(dst, xp + gr * HW + cq * 4);
            else
                *reinterpret_cast<float4*>(dst) = make_float4(0.f, 0.f, 0.f, 0.f);
        }
    };

    fill(0, 0);
    CP_COMMIT();

    float w[9];
    const float* wp = wdyn + (size_t)plane * 9;
#pragma unroll
    for (int i = 0; i < 9; i++) w[i] = __ldg(wp + i);
    const float bv = __ldg(bias + ch);

    fill(1, ROWS);
    CP_COMMIT();

    const int cx = threadIdx.x * 4;

    auto compute = [&](int buf, int row0) {
#pragma unroll
        for (int j = 0; j < 2; j++) {
            const int rt = threadIdx.y * 2 + j;
            float a0 = bv, a1 = bv, a2 = bv, a3 = bv;
#pragma unroll
            for (int dy = 0; dy < 3; dy++) {
                const float4 v = *reinterpret_cast<const float4*>(&tile[buf][rt + dy][cx]);
                float vl = __shfl_up_sync(0xffffffffu, v.w, 1);
                float vr = __shfl_down_sync(0xffffffffu, v.x, 1);
                if (lane == 0)  vl = 0.f;
                if (lane == 31) vr = 0.f;
                const float w0 = w[dy * 3 + 0], w1_ = w[dy * 3 + 1], w2_ = w[dy * 3 + 2];
                a0 += vl  * w0 + v.x * w1_ + v.y * w2_;
                a1 += v.x * w0 + v.y * w1_ + v.z * w2_;
                a2 += v.y * w0 + v.z * w1_ + v.w * w2_;
                a3 += v.z * w0 + v.w * w1_ + vr  * w2_;
            }
            float4 o; o.x = a0; o.y = a1; o.z = a2; o.w = a3;
            __stcs(reinterpret_cast<float4*>(op + (row0 + rt) * HW + cx), o);
        }
    };

    int buf = 0;
#pragma unroll
    for (int t = 0; t < NTILES; t++) {
        if (t < NTILES - 1) { CP_WAIT1(); } else { CP_WAIT0(); }
        __syncthreads();
        compute(buf, t * ROWS);
        __syncthreads();
        if (t + 2 < NTILES) {
            const int nb = (buf + 2) % 3;
            fill(nb, (t + 2) * ROWS);
            CP_COMMIT();
        }
        buf = (buf + 1) % 3;
    }
}

// ---------------------------------------------------------------------------
// Launch: memset counters (independent, runs first) -> pool(+weights) -> conv
// ---------------------------------------------------------------------------
extern "C" void kernel_launch(void* const* d_in, const int* in_sizes, int n_in,
                              void* d_out, int out_size) {
    const float* x     = (const float*)d_in[0];
    const float* w1    = (const float*)d_in[1];
    const float* gamma = (const float*)d_in[2];
    const float* beta  = (const float*)d_in[3];
    const float* rmean = (const float*)d_in[4];
    const float* rvar  = (const float*)d_in[5];
    const float* w2    = (const float*)d_in[6];
    const float* b2    = (const float*)d_in[7];
    const float* bias  = (const float*)d_in[8];
    float* out = (float*)d_out;

    const int B = in_sizes[0] / (C_DIM * PLANE);
    const int planes = B * C_DIM;

    float* pooled;
    float* wdyn;
    int* cnt;
    cudaGetSymbolAddress((void**)&pooled, g_pooled);
    cudaGetSymbolAddress((void**)&wdyn, g_wdyn);
    cudaGetSymbolAddress((void**)&cnt, g_cnt);

    cudaMemsetAsync(cnt, 0, MAX_B * sizeof(int));
    pool_kernel<<<planes, 256>>>(x, w1, gamma, beta, rmean, rvar, w2, b2,
                                 pooled, wdyn, cnt);
    dim3 block(32, 8);
    dwconv_kernel<<<planes, block>>>(x, wdyn, bias, out);
}